// round 14
// baseline (speedup 1.0000x reference)
#include <cuda_runtime.h>
#include <cuda_fp16.h>
#include <math.h>
#include <stdint.h>

#define V     49152
#define BATCH 2
#define M     (BATCH*V)      // 98304
#define DEG   20
#define CIN   128
#define CMID  64

// ---------------- scratch (device globals; zero-initialized) ------------------
__device__ __align__(128) __half g_y1h[M*CMID];
__device__ __align__(128) __half g_t1h[M*CMID];
__device__ __align__(128) __half g_t2h[M*CMID];
__device__ __align__(128) __half g_y2h[M*CMID];
__device__ __align__(128) __half g_y3h[M*CIN];
__device__ __align__(128) float g_sum[3*128];
__device__ __align__(128) float g_sq [3*128];
__device__ __align__(128) float g_scale[3*128];
__device__ __align__(128) float g_shift[3*128];
__device__ unsigned int g_ctr[3];

// ---------------- PTX helpers --------------------------------------------------
__device__ __forceinline__ void mma_h(float* c, const uint32_t* a, const uint32_t* b) {
    asm volatile(
        "mma.sync.aligned.m16n8k16.row.col.f32.f16.f16.f32 "
        "{%0,%1,%2,%3}, {%4,%5,%6,%7}, {%8,%9}, {%0,%1,%2,%3};"
        : "+f"(c[0]), "+f"(c[1]), "+f"(c[2]), "+f"(c[3])
        : "r"(a[0]), "r"(a[1]), "r"(a[2]), "r"(a[3]), "r"(b[0]), "r"(b[1]));
}
__device__ __forceinline__ void ldsm_x4(uint32_t* r, uint32_t addr) {
    asm volatile("ldmatrix.sync.aligned.m8n8.x4.shared.b16 {%0,%1,%2,%3}, [%4];"
        : "=r"(r[0]), "=r"(r[1]), "=r"(r[2]), "=r"(r[3]) : "r"(addr));
}
__device__ __forceinline__ uint32_t smem_u32(const void* p) {
    uint32_t a;
    asm("{ .reg .u64 t; cvta.to.shared.u64 t, %1; cvt.u32.u64 %0, t; }" : "=r"(a) : "l"(p));
    return a;
}

// ---------------- tensor-core GEMM (HMMA fp16, chunked, ldmatrix x4) -----------
// Y[128-row tile, NOUT] = sum_s A_s[tile, K] @ W[s*K.., NOUT] + bias
// A: plain fp16 in smem; W: fp16 hi/lo split -> 2 MMA passes.
// SRCF32: source is fp32 (converted while staging). BN0: fused BN+ReLU applied
// to source 0 while staging. OUTF16: Y stored as __half.
// Fused BN-stats epilogue (fp32 accumulators); last block computes this layer's
// scale/shift and resets the accumulators (replay-safe).
template<int K, int NOUT, int NSRC, bool BN0, bool SRCF32, bool OUTF16>
__global__ void __launch_bounds__(256) gemm_mma(
    const void* __restrict__ A0v, const void* __restrict__ A1v, const void* __restrict__ A2v,
    const float* __restrict__ W, const float* __restrict__ bias,
    const float* __restrict__ bsc, const float* __restrict__ bsh,
    void* __restrict__ Yv,
    const float* __restrict__ gamma, const float* __restrict__ beta,
    float* __restrict__ gs, float* __restrict__ gq,
    float* __restrict__ oscale, float* __restrict__ oshift,
    unsigned int* __restrict__ ctr)
{
    constexpr int KT   = NSRC*K;
    constexpr int NCH  = KT/64;               // 64-col chunks
    constexpr int SA   = 72;                  // padded row stride (fp16 elems)
    constexpr int WCH  = NOUT*SA*2;           // bytes per W chunk (hi or lo)
    constexpr int OFF_A = NCH*2*WCH;          // single A buffer after W chunks

    extern __shared__ char smc[];
    const uint32_t sbase = smem_u32(smc);

    const int t    = threadIdx.x;
    const int wid  = t >> 5, lane = t & 31;
    const int row0 = blockIdx.x * 128;
    const int g    = lane >> 2, tg = lane & 3;
    const int rb   = wid*16;

    // ---- stage W: Wt[n][k] = W[kt][n] per chunk, fp16 hi/lo ----
    for (int i = t; i < KT*NOUT; i += 256) {
        int n = i % NOUT, kt = i / NOUT;
        int c = kt >> 6, kk = kt & 63;
        float w = W[i];
        __half h = __float2half_rn(w);
        *(__half*)(smc + c*2*WCH + (n*SA + kk)*2)       = h;
        *(__half*)(smc + c*2*WCH + WCH + (n*SA + kk)*2) = __float2half_rn(w - __half2float(h));
    }

    constexpr int NB = NOUT/8;
    float acc[NB][4];
    #pragma unroll
    for (int nb = 0; nb < NB; ++nb)
        acc[nb][0] = acc[nb][1] = acc[nb][2] = acc[nb][3] = 0.f;

    // lane-address pattern shared by A-frag x4 and W-frag x4 loads
    const uint32_t lpat = (((lane & 15))*SA + (lane >> 4)*8)*2;
    const uint32_t aAd  = sbase + OFF_A + rb*SA*2 + lpat;

    #pragma unroll
    for (int c = 0; c < NCH; ++c) {
        const int s  = (c*64) / K;
        const int ko = (c*64) % K;
        const void* Av = (s == 0) ? A0v : ((s == 1) ? A1v : A2v);

        __syncthreads();   // W staged (c==0) / previous chunk consumed
        if (!SRCF32) {
            const __half* A = (const __half*)Av;
            for (int i = t; i < 128*8; i += 256) {
                int r = i >> 3, c8 = i & 7;
                uint4 u = *(const uint4*)(A + (size_t)(row0 + r)*K + ko + c8*8);
                if (BN0 && s == 0) {
                    float4 sc0 = *(const float4*)(bsc + ko + c8*8);
                    float4 sc1 = *(const float4*)(bsc + ko + c8*8 + 4);
                    float4 sh0 = *(const float4*)(bsh + ko + c8*8);
                    float4 sh1 = *(const float4*)(bsh + ko + c8*8 + 4);
                    const __half2* hp = (const __half2*)&u;
                    float2 f0 = __half22float2(hp[0]);
                    float2 f1 = __half22float2(hp[1]);
                    float2 f2 = __half22float2(hp[2]);
                    float2 f3 = __half22float2(hp[3]);
                    __half2 o0 = __floats2half2_rn(fmaxf(fmaf(f0.x, sc0.x, sh0.x), 0.f),
                                                   fmaxf(fmaf(f0.y, sc0.y, sh0.y), 0.f));
                    __half2 o1 = __floats2half2_rn(fmaxf(fmaf(f1.x, sc0.z, sh0.z), 0.f),
                                                   fmaxf(fmaf(f1.y, sc0.w, sh0.w), 0.f));
                    __half2 o2 = __floats2half2_rn(fmaxf(fmaf(f2.x, sc1.x, sh1.x), 0.f),
                                                   fmaxf(fmaf(f2.y, sc1.y, sh1.y), 0.f));
                    __half2 o3 = __floats2half2_rn(fmaxf(fmaf(f3.x, sc1.z, sh1.z), 0.f),
                                                   fmaxf(fmaf(f3.y, sc1.w, sh1.w), 0.f));
                    u.x = *(uint32_t*)&o0; u.y = *(uint32_t*)&o1;
                    u.z = *(uint32_t*)&o2; u.w = *(uint32_t*)&o3;
                }
                *(uint4*)(smc + OFF_A + (r*SA + c8*8)*2) = u;
            }
        } else {
            const float* A = (const float*)Av;
            for (int i = t; i < 128*16; i += 256) {
                int r = i >> 4, c4 = i & 15;
                float4 v = *(const float4*)(A + (size_t)(row0 + r)*K + ko + c4*4);
                if (BN0 && s == 0) {
                    float4 sc = *(const float4*)(bsc + ko + c4*4);
                    float4 sh = *(const float4*)(bsh + ko + c4*4);
                    v.x = fmaxf(fmaf(v.x, sc.x, sh.x), 0.f);
                    v.y = fmaxf(fmaf(v.y, sc.y, sh.y), 0.f);
                    v.z = fmaxf(fmaf(v.z, sc.z, sh.z), 0.f);
                    v.w = fmaxf(fmaf(v.w, sc.w, sh.w), 0.f);
                }
                __half2 h01 = __floats2half2_rn(v.x, v.y);
                __half2 h23 = __floats2half2_rn(v.z, v.w);
                uint2 o; o.x = *(uint32_t*)&h01; o.y = *(uint32_t*)&h23;
                *(uint2*)(smc + OFF_A + (r*SA + c4*4)*2) = o;
            }
        }
        __syncthreads();

        const uint32_t wch = sbase + c*2*WCH + lpat;
        #pragma unroll
        for (int kk = 0; kk < 4; ++kk) {
            uint32_t ah[4];
            ldsm_x4(ah, aAd + kk*32);
            #pragma unroll
            for (int nb2 = 0; nb2 < NB/2; ++nb2) {
                uint32_t bh[4], bl[4];
                uint32_t wa = wch + nb2*16*SA*2 + kk*32;
                ldsm_x4(bh, wa);
                ldsm_x4(bl, wa + WCH);
                uint32_t b0h[2] = {bh[0], bh[2]}, b1h[2] = {bh[1], bh[3]};
                uint32_t b0l[2] = {bl[0], bl[2]}, b1l[2] = {bl[1], bl[3]};
                mma_h(acc[2*nb2],   ah, b0h);   // A*Whi
                mma_h(acc[2*nb2],   ah, b0l);   // A*Wlo
                mma_h(acc[2*nb2+1], ah, b1h);
                mma_h(acc[2*nb2+1], ah, b1l);
            }
        }
    }

    __syncthreads();   // compute done -> smem reusable for stats reduction
    float* redS = (float*)smc;               // [8][NOUT]
    float* redQ = (float*)smc + 8*NOUT;      // [8][NOUT]

    // ---- store (fp32 or fp16) + per-warp column partials (always fp32) ----
    {
        #pragma unroll
        for (int nb = 0; nb < NB; ++nb) {
            int c = nb*8 + tg*2;
            float2 bb = __ldg((const float2*)(bias + c));
            float y00 = acc[nb][0] + bb.x, y01 = acc[nb][1] + bb.y;
            float y80 = acc[nb][2] + bb.x, y81 = acc[nb][3] + bb.y;
            if (OUTF16) {
                __half* y0 = (__half*)Yv + (size_t)(row0 + rb + g)*NOUT;
                __half* y8 = (__half*)Yv + (size_t)(row0 + rb + g + 8)*NOUT;
                __half2 p0 = __floats2half2_rn(y00, y01);
                __half2 p8 = __floats2half2_rn(y80, y81);
                *(__half2*)(y0 + c) = p0;
                *(__half2*)(y8 + c) = p8;
            } else {
                float* y0 = (float*)Yv + (size_t)(row0 + rb + g)*NOUT;
                float* y8 = (float*)Yv + (size_t)(row0 + rb + g + 8)*NOUT;
                *(float2*)(y0 + c) = make_float2(y00, y01);
                *(float2*)(y8 + c) = make_float2(y80, y81);
            }
            float s0 = y00 + y80, q0 = y00*y00 + y80*y80;
            float s1 = y01 + y81, q1 = y01*y01 + y81*y81;
            #pragma unroll
            for (int off = 4; off <= 16; off <<= 1) {
                s0 += __shfl_xor_sync(0xffffffffu, s0, off);
                q0 += __shfl_xor_sync(0xffffffffu, q0, off);
                s1 += __shfl_xor_sync(0xffffffffu, s1, off);
                q1 += __shfl_xor_sync(0xffffffffu, q1, off);
            }
            if (lane < 4) {
                redS[wid*NOUT + c]     = s0;
                redS[wid*NOUT + c + 1] = s1;
                redQ[wid*NOUT + c]     = q0;
                redQ[wid*NOUT + c + 1] = q1;
            }
        }
    }
    __syncthreads();

    if (t < NOUT) {
        float s = 0.f, q = 0.f;
        #pragma unroll
        for (int w = 0; w < 8; ++w) { s += redS[w*NOUT + t]; q += redQ[w*NOUT + t]; }
        atomicAdd(&gs[t], s);
        atomicAdd(&gq[t], q);
    }
    __threadfence();
    __syncthreads();

    __shared__ bool s_last;
    if (t == 0) s_last = (atomicAdd(ctr, 1u) == (unsigned)gridDim.x - 1u);
    __syncthreads();
    if (s_last) {
        if (t < NOUT) {
            float mean = gs[t] * (1.f/(float)M);
            float var  = gq[t] * (1.f/(float)M) - mean*mean;
            float sc   = gamma[t] * rsqrtf(var + 1e-5f);
            oscale[t] = sc;
            oshift[t] = beta[t] - mean*sc;
            gs[t] = 0.f; gq[t] = 0.f;      // replay-safe reset
        }
        if (t == 0) *ctr = 0u;
    }
}

// ---------------- SpMM fp16: 2 rows/warp, 8 channels/lane, MLP-batched ---------
// GBN: apply BN+ReLU (sc/sh) to gathered X values (fp32, on the fly).
// CHEB: out = 2*acc - bnrelu(X0h)  (X0 BN uses the same sc/sh set).
template<bool GBN, bool CHEB>
__global__ void __launch_bounds__(256) spmm_f16(
    const int*   __restrict__ cols,
    const float* __restrict__ vals,
    const __half* __restrict__ X,
    const __half* __restrict__ X0h,
    const float* __restrict__ sc_g,
    const float* __restrict__ sh_g,
    __half* __restrict__ Yo)
{
    int warp = (blockIdx.x * blockDim.x + threadIdx.x) >> 5;
    int lane = threadIdx.x & 31;
    int r = warp*2 + (lane >> 4);
    if (r >= V) return;
    const int b  = (lane >> 3) & 1;
    const int f8 = lane & 7;
    const __half* Xb = X + (size_t)b*V*CMID + f8*8;

    float scv[8], shv[8];
    if (GBN || CHEB) {
        float4 s0 = *(const float4*)(sc_g + f8*8);
        float4 s1 = *(const float4*)(sc_g + f8*8 + 4);
        float4 h0 = *(const float4*)(sh_g + f8*8);
        float4 h1 = *(const float4*)(sh_g + f8*8 + 4);
        scv[0]=s0.x; scv[1]=s0.y; scv[2]=s0.z; scv[3]=s0.w;
        scv[4]=s1.x; scv[5]=s1.y; scv[6]=s1.z; scv[7]=s1.w;
        shv[0]=h0.x; shv[1]=h0.y; shv[2]=h0.z; shv[3]=h0.w;
        shv[4]=h1.x; shv[5]=h1.y; shv[6]=h1.z; shv[7]=h1.w;
    }

    float acc[8];
    #pragma unroll
    for (int j = 0; j < 8; ++j) acc[j] = 0.f;

    // self edge (col == cols[r])
    {
        int c = __ldg(&cols[r]); float v = __ldg(&vals[r]);
        uint4 u = *(const uint4*)(Xb + (size_t)c*CMID);
        const __half2* hp = (const __half2*)&u;
        #pragma unroll
        for (int j = 0; j < 4; ++j) {
            float2 f = __half22float2(hp[j]);
            float x0 = f.x, x1 = f.y;
            if (GBN) {
                x0 = fmaxf(fmaf(x0, scv[2*j],   shv[2*j]),   0.f);
                x1 = fmaxf(fmaf(x1, scv[2*j+1], shv[2*j+1]), 0.f);
            }
            acc[2*j]   += v*x0;
            acc[2*j+1] += v*x1;
        }
    }
    // 20 neighbors in batches of 4 (4 independent gathers in flight)
    const int base = V + r*DEG;
    #pragma unroll
    for (int g4 = 0; g4 < 5; ++g4) {
        int   cc[4]; float vv[4];
        #pragma unroll
        for (int e = 0; e < 4; ++e) {
            cc[e] = __ldg(&cols[base + g4*4 + e]);
            vv[e] = __ldg(&vals[base + g4*4 + e]);
        }
        uint4 u[4];
        #pragma unroll
        for (int e = 0; e < 4; ++e)
            u[e] = *(const uint4*)(Xb + (size_t)cc[e]*CMID);
        #pragma unroll
        for (int e = 0; e < 4; ++e) {
            const __half2* hp = (const __half2*)&u[e];
            float v = vv[e];
            #pragma unroll
            for (int j = 0; j < 4; ++j) {
                float2 f = __half22float2(hp[j]);
                float x0 = f.x, x1 = f.y;
                if (GBN) {
                    x0 = fmaxf(fmaf(x0, scv[2*j],   shv[2*j]),   0.f);
                    x1 = fmaxf(fmaf(x1, scv[2*j+1], shv[2*j+1]), 0.f);
                }
                acc[2*j]   += v*x0;
                acc[2*j+1] += v*x1;
            }
        }
    }

    size_t o = (size_t)b*V*CMID + (size_t)r*CMID + f8*8;
    if (CHEB) {
        uint4 u0 = *(const uint4*)(X0h + o);
        const __half2* hp = (const __half2*)&u0;
        #pragma unroll
        for (int j = 0; j < 4; ++j) {
            float2 f = __half22float2(hp[j]);
            float x0 = fmaxf(fmaf(f.x, scv[2*j],   shv[2*j]),   0.f);
            float x1 = fmaxf(fmaf(f.y, scv[2*j+1], shv[2*j+1]), 0.f);
            acc[2*j]   = 2.f*acc[2*j]   - x0;
            acc[2*j+1] = 2.f*acc[2*j+1] - x1;
        }
    }
    __half2 outp[4];
    #pragma unroll
    for (int j = 0; j < 4; ++j) outp[j] = __floats2half2_rn(acc[2*j], acc[2*j+1]);
    *(uint4*)(Yo + o) = *(uint4*)outp;
}

// ---------------- final BN apply + ReLU: fp16 in -> fp32 out -------------------
template<int C>
__global__ void bnrelu_out_kernel(const __half* __restrict__ Yin,
                                  float* __restrict__ Out,
                                  const float* __restrict__ scale,
                                  const float* __restrict__ shift)
{
    int i4 = blockIdx.x * blockDim.x + threadIdx.x;
    constexpr int TOT4 = M*C/4;
    if (i4 >= TOT4) return;
    int c4 = i4 % (C/4);
    uint2 u = ((const uint2*)Yin)[i4];
    const __half2* hp = (const __half2*)&u;
    float2 f0 = __half22float2(hp[0]);
    float2 f1 = __half22float2(hp[1]);
    float4 sc = ((const float4*)scale)[c4];
    float4 sh = ((const float4*)shift)[c4];
    float4 o;
    o.x = fmaxf(fmaf(f0.x, sc.x, sh.x), 0.f);
    o.y = fmaxf(fmaf(f0.y, sc.y, sh.y), 0.f);
    o.z = fmaxf(fmaf(f1.x, sc.z, sh.z), 0.f);
    o.w = fmaxf(fmaf(f1.y, sc.w, sh.w), 0.f);
    ((float4*)Out)[i4] = o;
}

// ------------------------------------------------------------------------------
extern "C" void kernel_launch(void* const* d_in, const int* in_sizes, int n_in,
                              void* d_out, int out_size)
{
    const float* x    = (const float*)d_in[0];
    const int*   cols = (const int*)  d_in[2];
    const float* vals = (const float*)d_in[3];
    const float* W1   = (const float*)d_in[4];
    const float* b1   = (const float*)d_in[5];
    const float* g1   = (const float*)d_in[6];
    const float* be1  = (const float*)d_in[7];
    const float* W2   = (const float*)d_in[8];
    const float* b2   = (const float*)d_in[9];
    const float* g2   = (const float*)d_in[10];
    const float* be2  = (const float*)d_in[11];
    const float* W3   = (const float*)d_in[12];
    const float* b3   = (const float*)d_in[13];
    const float* g3   = (const float*)d_in[14];
    const float* be3  = (const float*)d_in[15];
    float* out = (float*)d_out;

    float *gsum, *gsq, *gscale, *gshift;
    __half *y1h, *t1h, *t2h, *y2h, *y3h;
    unsigned int* ctr;
    cudaGetSymbolAddress((void**)&y1h, g_y1h);
    cudaGetSymbolAddress((void**)&t1h, g_t1h);
    cudaGetSymbolAddress((void**)&t2h, g_t2h);
    cudaGetSymbolAddress((void**)&y2h, g_y2h);
    cudaGetSymbolAddress((void**)&y3h, g_y3h);
    cudaGetSymbolAddress((void**)&gsum,   g_sum);
    cudaGetSymbolAddress((void**)&gsq,    g_sq);
    cudaGetSymbolAddress((void**)&gscale, g_scale);
    cudaGetSymbolAddress((void**)&gshift, g_shift);
    cudaGetSymbolAddress((void**)&ctr,    g_ctr);

    // smem (SA=72): W chunks (hi+lo) + single fp16 A buffer (18432 B)
    const int smem1 = 2*2*(64*72*2)  + (128*72*2);      // 55296 -> 4 CTAs/SM
    const int smem2 = 3*2*(64*72*2)  + (128*72*2);      // 73728 -> 3 CTAs/SM
    const int smem3 = 1*2*(128*72*2) + (128*72*2);      // 55296 -> 4 CTAs/SM
    cudaFuncSetAttribute(gemm_mma<128, 64, 1, false, true , true>, cudaFuncAttributeMaxDynamicSharedMemorySize, smem1);
    cudaFuncSetAttribute(gemm_mma< 64, 64, 3, true , false, true>, cudaFuncAttributeMaxDynamicSharedMemorySize, smem2);
    cudaFuncSetAttribute(gemm_mma< 64,128, 1, true , false, true>, cudaFuncAttributeMaxDynamicSharedMemorySize, smem3);

    const int GEMM_GRID   = M / 128;           // 768
    const int SPMM_GRID   = V/2 * 32 / 256;    // 3072
    const int BNR_GRID128 = M*CIN/4/256;       // 12288

    // ---- layer 1: y1h = fp16(x @ W1 + b1) ; fused stats+finalize ----
    gemm_mma<128, 64, 1, false, true, true><<<GEMM_GRID, 256, smem1>>>(
        x, nullptr, nullptr, W1, b1, nullptr, nullptr, y1h,
        g1, be1, gsum + 0, gsq + 0, gscale + 0, gshift + 0, ctr + 0);

    // ---- layer 2: Chebyshev K=3; h1 = bnrelu(y1h) materialized on the fly ----
    spmm_f16<true , false><<<SPMM_GRID, 256>>>(cols, vals, y1h, nullptr,
                                               gscale + 0, gshift + 0, t1h);  // t1 = S h1
    spmm_f16<false, true ><<<SPMM_GRID, 256>>>(cols, vals, t1h, y1h,
                                               gscale + 0, gshift + 0, t2h);  // t2 = 2 S t1 - h1
    gemm_mma<64, 64, 3, true, false, true><<<GEMM_GRID, 256, smem2>>>(
        y1h, t1h, t2h, W2, b2, gscale + 0, gshift + 0, y2h,
        g2, be2, gsum + 128, gsq + 128, gscale + 128, gshift + 128, ctr + 1);

    // ---- layer 3: y3h = fp16( bnrelu(y2h) @ W3 + b3 ) ; out = bnrelu(y3h) ----
    gemm_mma<64, 128, 1, true, false, true><<<GEMM_GRID, 256, smem3>>>(
        y2h, nullptr, nullptr, W3, b3, gscale + 128, gshift + 128, y3h,
        g3, be3, gsum + 256, gsq + 256, gscale + 256, gshift + 256, ctr + 2);
    bnrelu_out_kernel<CIN><<<BNR_GRID128, 256>>>(y3h, out, gscale + 256, gshift + 256);
}

// round 15
// speedup vs baseline: 1.0248x; 1.0248x over previous
#include <cuda_runtime.h>
#include <cuda_fp16.h>
#include <math.h>
#include <stdint.h>

#define V     49152
#define BATCH 2
#define M     (BATCH*V)      // 98304
#define DEG   20
#define CIN   128
#define CMID  64

// ---------------- scratch (device globals; zero-initialized) ------------------
__device__ __align__(128) __half g_y1h[M*CMID];
__device__ __align__(128) __half g_h1h[M*CMID];
__device__ __align__(128) __half g_t1h[M*CMID];
__device__ __align__(128) __half g_t2h[M*CMID];
__device__ __align__(128) __half g_y2h[M*CMID];
__device__ __align__(128) __half g_y3h[M*CIN];
__device__ __align__(128) float g_sum[3*128];
__device__ __align__(128) float g_sq [3*128];
__device__ __align__(128) float g_scale[3*128];
__device__ __align__(128) float g_shift[3*128];
__device__ unsigned int g_ctr[3];

// ---------------- PTX helpers --------------------------------------------------
__device__ __forceinline__ void mma_h(float* c, const uint32_t* a, const uint32_t* b) {
    asm volatile(
        "mma.sync.aligned.m16n8k16.row.col.f32.f16.f16.f32 "
        "{%0,%1,%2,%3}, {%4,%5,%6,%7}, {%8,%9}, {%0,%1,%2,%3};"
        : "+f"(c[0]), "+f"(c[1]), "+f"(c[2]), "+f"(c[3])
        : "r"(a[0]), "r"(a[1]), "r"(a[2]), "r"(a[3]), "r"(b[0]), "r"(b[1]));
}
__device__ __forceinline__ void ldsm_x4(uint32_t* r, uint32_t addr) {
    asm volatile("ldmatrix.sync.aligned.m8n8.x4.shared.b16 {%0,%1,%2,%3}, [%4];"
        : "=r"(r[0]), "=r"(r[1]), "=r"(r[2]), "=r"(r[3]) : "r"(addr));
}
__device__ __forceinline__ uint32_t smem_u32(const void* p) {
    uint32_t a;
    asm("{ .reg .u64 t; cvta.to.shared.u64 t, %1; cvt.u32.u64 %0, t; }" : "=r"(a) : "l"(p));
    return a;
}

// ---------------- tensor-core GEMM (HMMA fp16, chunked, ldmatrix x4) -----------
// Y[128-row tile, NOUT] = sum_s A_s[tile, K] @ W[s*K.., NOUT] + bias
// A: plain fp16 in smem; W: fp16 hi/lo split -> 2 MMA passes.
// SRCF32: source is fp32 (converted while staging). BN0: fused BN+ReLU applied
// to source 0 while staging. OUTF16: Y stored as __half.
// fp16-source multi-chunk path uses register prefetch to overlap next chunk's
// global loads with the current chunk's MMA compute.
// Fused BN-stats epilogue (fp32 accumulators); last block computes this layer's
// scale/shift and resets the accumulators (replay-safe).
template<int K, int NOUT, int NSRC, bool BN0, bool SRCF32, bool OUTF16>
__global__ void __launch_bounds__(256) gemm_mma(
    const void* __restrict__ A0v, const void* __restrict__ A1v, const void* __restrict__ A2v,
    const float* __restrict__ W, const float* __restrict__ bias,
    const float* __restrict__ bsc, const float* __restrict__ bsh,
    void* __restrict__ Yv,
    const float* __restrict__ gamma, const float* __restrict__ beta,
    float* __restrict__ gs, float* __restrict__ gq,
    float* __restrict__ oscale, float* __restrict__ oshift,
    unsigned int* __restrict__ ctr)
{
    constexpr int KT   = NSRC*K;
    constexpr int NCH  = KT/64;               // 64-col chunks
    constexpr int SA   = 72;                  // padded row stride (fp16 elems)
    constexpr int WCH  = NOUT*SA*2;           // bytes per W chunk (hi or lo)
    constexpr int OFF_A = NCH*2*WCH;          // single A buffer after W chunks
    constexpr bool PIPE = (!SRCF32) && (NCH > 1);

    extern __shared__ char smc[];
    const uint32_t sbase = smem_u32(smc);

    const int t    = threadIdx.x;
    const int wid  = t >> 5, lane = t & 31;
    const int row0 = blockIdx.x * 128;
    const int g    = lane >> 2, tg = lane & 3;
    const int rb   = wid*16;

    // ---- stage W: Wt[n][k] = W[kt][n] per chunk, fp16 hi/lo ----
    for (int i = t; i < KT*NOUT; i += 256) {
        int n = i % NOUT, kt = i / NOUT;
        int c = kt >> 6, kk = kt & 63;
        float w = W[i];
        __half h = __float2half_rn(w);
        *(__half*)(smc + c*2*WCH + (n*SA + kk)*2)       = h;
        *(__half*)(smc + c*2*WCH + WCH + (n*SA + kk)*2) = __float2half_rn(w - __half2float(h));
    }

    constexpr int NB = NOUT/8;
    float acc[NB][4];
    #pragma unroll
    for (int nb = 0; nb < NB; ++nb)
        acc[nb][0] = acc[nb][1] = acc[nb][2] = acc[nb][3] = 0.f;

    // lane-address pattern shared by A-frag x4 and W-frag x4 loads
    const uint32_t lpat = (((lane & 15))*SA + (lane >> 4)*8)*2;
    const uint32_t aAd  = sbase + OFF_A + rb*SA*2 + lpat;

    // register prefetch (fp16-source pipelined path): chunk 0 (s=0, ko=0)
    uint4 pre[4];
    if (PIPE) {
        const __half* A = (const __half*)A0v;
        #pragma unroll
        for (int j = 0; j < 4; ++j) {
            int i = t + j*256;
            int r = i >> 3, c8 = i & 7;
            pre[j] = *(const uint4*)(A + (size_t)(row0 + r)*K + c8*8);
        }
    }

    #pragma unroll
    for (int c = 0; c < NCH; ++c) {
        const int s  = (c*64) / K;
        const int ko = (c*64) % K;

        __syncthreads();   // W staged (c==0) / previous chunk consumed
        if (PIPE) {
            // store prefetched regs to smem
            #pragma unroll
            for (int j = 0; j < 4; ++j) {
                int i = t + j*256;
                int r = i >> 3, c8 = i & 7;
                *(uint4*)(smc + OFF_A + (r*SA + c8*8)*2) = pre[j];
            }
            // issue next chunk's global loads (latency hidden under compute)
            if (c + 1 < NCH) {
                const int sn  = ((c+1)*64) / K;
                const int kon = ((c+1)*64) % K;
                const __half* An = (const __half*)((sn == 0) ? A0v : ((sn == 1) ? A1v : A2v));
                #pragma unroll
                for (int j = 0; j < 4; ++j) {
                    int i = t + j*256;
                    int r = i >> 3, c8 = i & 7;
                    pre[j] = *(const uint4*)(An + (size_t)(row0 + r)*K + kon + c8*8);
                }
            }
        } else if (!SRCF32) {
            // single-chunk fp16 source (optional fused BN+ReLU on source 0)
            const __half* A = (const __half*)A0v;
            for (int i = t; i < 128*8; i += 256) {
                int r = i >> 3, c8 = i & 7;
                uint4 u = *(const uint4*)(A + (size_t)(row0 + r)*K + ko + c8*8);
                if (BN0 && s == 0) {
                    float4 sc0 = *(const float4*)(bsc + ko + c8*8);
                    float4 sc1 = *(const float4*)(bsc + ko + c8*8 + 4);
                    float4 sh0 = *(const float4*)(bsh + ko + c8*8);
                    float4 sh1 = *(const float4*)(bsh + ko + c8*8 + 4);
                    const __half2* hp = (const __half2*)&u;
                    float2 f0 = __half22float2(hp[0]);
                    float2 f1 = __half22float2(hp[1]);
                    float2 f2 = __half22float2(hp[2]);
                    float2 f3 = __half22float2(hp[3]);
                    __half2 o0 = __floats2half2_rn(fmaxf(fmaf(f0.x, sc0.x, sh0.x), 0.f),
                                                   fmaxf(fmaf(f0.y, sc0.y, sh0.y), 0.f));
                    __half2 o1 = __floats2half2_rn(fmaxf(fmaf(f1.x, sc0.z, sh0.z), 0.f),
                                                   fmaxf(fmaf(f1.y, sc0.w, sh0.w), 0.f));
                    __half2 o2 = __floats2half2_rn(fmaxf(fmaf(f2.x, sc1.x, sh1.x), 0.f),
                                                   fmaxf(fmaf(f2.y, sc1.y, sh1.y), 0.f));
                    __half2 o3 = __floats2half2_rn(fmaxf(fmaf(f3.x, sc1.z, sh1.z), 0.f),
                                                   fmaxf(fmaf(f3.y, sc1.w, sh1.w), 0.f));
                    u.x = *(uint32_t*)&o0; u.y = *(uint32_t*)&o1;
                    u.z = *(uint32_t*)&o2; u.w = *(uint32_t*)&o3;
                }
                *(uint4*)(smc + OFF_A + (r*SA + c8*8)*2) = u;
            }
        } else {
            const float* A = (const float*)((s == 0) ? A0v : ((s == 1) ? A1v : A2v));
            for (int i = t; i < 128*16; i += 256) {
                int r = i >> 4, c4 = i & 15;
                float4 v = *(const float4*)(A + (size_t)(row0 + r)*K + ko + c4*4);
                if (BN0 && s == 0) {
                    float4 sc = *(const float4*)(bsc + ko + c4*4);
                    float4 sh = *(const float4*)(bsh + ko + c4*4);
                    v.x = fmaxf(fmaf(v.x, sc.x, sh.x), 0.f);
                    v.y = fmaxf(fmaf(v.y, sc.y, sh.y), 0.f);
                    v.z = fmaxf(fmaf(v.z, sc.z, sh.z), 0.f);
                    v.w = fmaxf(fmaf(v.w, sc.w, sh.w), 0.f);
                }
                __half2 h01 = __floats2half2_rn(v.x, v.y);
                __half2 h23 = __floats2half2_rn(v.z, v.w);
                uint2 o; o.x = *(uint32_t*)&h01; o.y = *(uint32_t*)&h23;
                *(uint2*)(smc + OFF_A + (r*SA + c4*4)*2) = o;
            }
        }
        __syncthreads();

        const uint32_t wch = sbase + c*2*WCH + lpat;
        #pragma unroll
        for (int kk = 0; kk < 4; ++kk) {
            uint32_t ah[4];
            ldsm_x4(ah, aAd + kk*32);
            #pragma unroll
            for (int nb2 = 0; nb2 < NB/2; ++nb2) {
                uint32_t bh[4], bl[4];
                uint32_t wa = wch + nb2*16*SA*2 + kk*32;
                ldsm_x4(bh, wa);
                ldsm_x4(bl, wa + WCH);
                uint32_t b0h[2] = {bh[0], bh[2]}, b1h[2] = {bh[1], bh[3]};
                uint32_t b0l[2] = {bl[0], bl[2]}, b1l[2] = {bl[1], bl[3]};
                mma_h(acc[2*nb2],   ah, b0h);   // A*Whi
                mma_h(acc[2*nb2],   ah, b0l);   // A*Wlo
                mma_h(acc[2*nb2+1], ah, b1h);
                mma_h(acc[2*nb2+1], ah, b1l);
            }
        }
    }

    __syncthreads();   // compute done -> smem reusable for stats reduction
    float* redS = (float*)smc;               // [8][NOUT]
    float* redQ = (float*)smc + 8*NOUT;      // [8][NOUT]

    // ---- store (fp32 or fp16) + per-warp column partials (always fp32) ----
    {
        #pragma unroll
        for (int nb = 0; nb < NB; ++nb) {
            int c = nb*8 + tg*2;
            float2 bb = __ldg((const float2*)(bias + c));
            float y00 = acc[nb][0] + bb.x, y01 = acc[nb][1] + bb.y;
            float y80 = acc[nb][2] + bb.x, y81 = acc[nb][3] + bb.y;
            if (OUTF16) {
                __half* y0 = (__half*)Yv + (size_t)(row0 + rb + g)*NOUT;
                __half* y8 = (__half*)Yv + (size_t)(row0 + rb + g + 8)*NOUT;
                __half2 p0 = __floats2half2_rn(y00, y01);
                __half2 p8 = __floats2half2_rn(y80, y81);
                *(__half2*)(y0 + c) = p0;
                *(__half2*)(y8 + c) = p8;
            } else {
                float* y0 = (float*)Yv + (size_t)(row0 + rb + g)*NOUT;
                float* y8 = (float*)Yv + (size_t)(row0 + rb + g + 8)*NOUT;
                *(float2*)(y0 + c) = make_float2(y00, y01);
                *(float2*)(y8 + c) = make_float2(y80, y81);
            }
            float s0 = y00 + y80, q0 = y00*y00 + y80*y80;
            float s1 = y01 + y81, q1 = y01*y01 + y81*y81;
            #pragma unroll
            for (int off = 4; off <= 16; off <<= 1) {
                s0 += __shfl_xor_sync(0xffffffffu, s0, off);
                q0 += __shfl_xor_sync(0xffffffffu, q0, off);
                s1 += __shfl_xor_sync(0xffffffffu, s1, off);
                q1 += __shfl_xor_sync(0xffffffffu, q1, off);
            }
            if (lane < 4) {
                redS[wid*NOUT + c]     = s0;
                redS[wid*NOUT + c + 1] = s1;
                redQ[wid*NOUT + c]     = q0;
                redQ[wid*NOUT + c + 1] = q1;
            }
        }
    }
    __syncthreads();

    if (t < NOUT) {
        float s = 0.f, q = 0.f;
        #pragma unroll
        for (int w = 0; w < 8; ++w) { s += redS[w*NOUT + t]; q += redQ[w*NOUT + t]; }
        atomicAdd(&gs[t], s);
        atomicAdd(&gq[t], q);
    }
    __threadfence();
    __syncthreads();

    __shared__ bool s_last;
    if (t == 0) s_last = (atomicAdd(ctr, 1u) == (unsigned)gridDim.x - 1u);
    __syncthreads();
    if (s_last) {
        if (t < NOUT) {
            float mean = gs[t] * (1.f/(float)M);
            float var  = gq[t] * (1.f/(float)M) - mean*mean;
            float sc   = gamma[t] * rsqrtf(var + 1e-5f);
            oscale[t] = sc;
            oshift[t] = beta[t] - mean*sc;
            gs[t] = 0.f; gq[t] = 0.f;      // replay-safe reset
        }
        if (t == 0) *ctr = 0u;
    }
}

// ---------------- SpMM fp16: 2 rows/warp, 8 fp16 channels/lane (R13 form) ------
template<bool CHEB>
__global__ void spmm_f16(const int*   __restrict__ cols,
                         const float* __restrict__ vals,
                         const __half* __restrict__ X,
                         const __half* __restrict__ X0h,
                         __half* __restrict__ Yo)
{
    int warp = (blockIdx.x * blockDim.x + threadIdx.x) >> 5;
    int lane = threadIdx.x & 31;
    int r = warp*2 + (lane >> 4);
    if (r >= V) return;
    const int b  = (lane >> 3) & 1;
    const int f8 = lane & 7;
    const __half* Xb = X + (size_t)b*V*CMID + f8*8;

    float acc[8];
    #pragma unroll
    for (int j = 0; j < 8; ++j) acc[j] = 0.f;

    {
        int c = __ldg(&cols[r]); float v = __ldg(&vals[r]);
        uint4 u = *(const uint4*)(Xb + (size_t)c*CMID);
        const __half2* hp = (const __half2*)&u;
        #pragma unroll
        for (int j = 0; j < 4; ++j) {
            float2 f = __half22float2(hp[j]);
            acc[2*j]   += v*f.x;
            acc[2*j+1] += v*f.y;
        }
    }
    const int base = V + r*DEG;
    #pragma unroll
    for (int d = 0; d < DEG; ++d) {
        int c = __ldg(&cols[base+d]); float v = __ldg(&vals[base+d]);
        uint4 u = *(const uint4*)(Xb + (size_t)c*CMID);
        const __half2* hp = (const __half2*)&u;
        #pragma unroll
        for (int j = 0; j < 4; ++j) {
            float2 f = __half22float2(hp[j]);
            acc[2*j]   += v*f.x;
            acc[2*j+1] += v*f.y;
        }
    }

    size_t o = (size_t)b*V*CMID + (size_t)r*CMID + f8*8;
    if (CHEB) {
        uint4 u0 = *(const uint4*)(X0h + o);
        const __half2* hp = (const __half2*)&u0;
        #pragma unroll
        for (int j = 0; j < 4; ++j) {
            float2 f = __half22float2(hp[j]);
            acc[2*j]   = 2.f*acc[2*j]   - f.x;
            acc[2*j+1] = 2.f*acc[2*j+1] - f.y;
        }
    }
    __half2 outp[4];
    #pragma unroll
    for (int j = 0; j < 4; ++j) outp[j] = __floats2half2_rn(acc[2*j], acc[2*j+1]);
    *(uint4*)(Yo + o) = *(uint4*)outp;
}

// ---------------- BN apply + ReLU: fp16 in -> fp16 out (layer-1) ---------------
__global__ void bnrelu_h2h_kernel(const __half* __restrict__ Yin,
                                  __half* __restrict__ H,
                                  const float* __restrict__ scale,
                                  const float* __restrict__ shift)
{
    int i4 = blockIdx.x * blockDim.x + threadIdx.x;
    constexpr int TOT4 = M*CMID/4;
    if (i4 >= TOT4) return;
    int c4 = i4 & (CMID/4 - 1);
    uint2 u = ((const uint2*)Yin)[i4];
    const __half2* hp = (const __half2*)&u;
    float2 f0 = __half22float2(hp[0]);
    float2 f1 = __half22float2(hp[1]);
    float4 sc = ((const float4*)scale)[c4];
    float4 sh = ((const float4*)shift)[c4];
    __half2 a = __floats2half2_rn(fmaxf(fmaf(f0.x, sc.x, sh.x), 0.f),
                                  fmaxf(fmaf(f0.y, sc.y, sh.y), 0.f));
    __half2 b = __floats2half2_rn(fmaxf(fmaf(f1.x, sc.z, sh.z), 0.f),
                                  fmaxf(fmaf(f1.y, sc.w, sh.w), 0.f));
    uint2 o; o.x = *(uint32_t*)&a; o.y = *(uint32_t*)&b;
    ((uint2*)H)[i4] = o;
}

// ---------------- final BN apply + ReLU: fp16 in -> fp32 out -------------------
template<int C>
__global__ void bnrelu_out_kernel(const __half* __restrict__ Yin,
                                  float* __restrict__ Out,
                                  const float* __restrict__ scale,
                                  const float* __restrict__ shift)
{
    int i4 = blockIdx.x * blockDim.x + threadIdx.x;
    constexpr int TOT4 = M*C/4;
    if (i4 >= TOT4) return;
    int c4 = i4 % (C/4);
    uint2 u = ((const uint2*)Yin)[i4];
    const __half2* hp = (const __half2*)&u;
    float2 f0 = __half22float2(hp[0]);
    float2 f1 = __half22float2(hp[1]);
    float4 sc = ((const float4*)scale)[c4];
    float4 sh = ((const float4*)shift)[c4];
    float4 o;
    o.x = fmaxf(fmaf(f0.x, sc.x, sh.x), 0.f);
    o.y = fmaxf(fmaf(f0.y, sc.y, sh.y), 0.f);
    o.z = fmaxf(fmaf(f1.x, sc.z, sh.z), 0.f);
    o.w = fmaxf(fmaf(f1.y, sc.w, sh.w), 0.f);
    ((float4*)Out)[i4] = o;
}

// ------------------------------------------------------------------------------
extern "C" void kernel_launch(void* const* d_in, const int* in_sizes, int n_in,
                              void* d_out, int out_size)
{
    const float* x    = (const float*)d_in[0];
    const int*   cols = (const int*)  d_in[2];
    const float* vals = (const float*)d_in[3];
    const float* W1   = (const float*)d_in[4];
    const float* b1   = (const float*)d_in[5];
    const float* g1   = (const float*)d_in[6];
    const float* be1  = (const float*)d_in[7];
    const float* W2   = (const float*)d_in[8];
    const float* b2   = (const float*)d_in[9];
    const float* g2   = (const float*)d_in[10];
    const float* be2  = (const float*)d_in[11];
    const float* W3   = (const float*)d_in[12];
    const float* b3   = (const float*)d_in[13];
    const float* g3   = (const float*)d_in[14];
    const float* be3  = (const float*)d_in[15];
    float* out = (float*)d_out;

    float *gsum, *gsq, *gscale, *gshift;
    __half *y1h, *h1h, *t1h, *t2h, *y2h, *y3h;
    unsigned int* ctr;
    cudaGetSymbolAddress((void**)&y1h, g_y1h);
    cudaGetSymbolAddress((void**)&h1h, g_h1h);
    cudaGetSymbolAddress((void**)&t1h, g_t1h);
    cudaGetSymbolAddress((void**)&t2h, g_t2h);
    cudaGetSymbolAddress((void**)&y2h, g_y2h);
    cudaGetSymbolAddress((void**)&y3h, g_y3h);
    cudaGetSymbolAddress((void**)&gsum,   g_sum);
    cudaGetSymbolAddress((void**)&gsq,    g_sq);
    cudaGetSymbolAddress((void**)&gscale, g_scale);
    cudaGetSymbolAddress((void**)&gshift, g_shift);
    cudaGetSymbolAddress((void**)&ctr,    g_ctr);

    // smem (SA=72): W chunks (hi+lo) + single fp16 A buffer (18432 B)
    const int smem1 = 2*2*(64*72*2)  + (128*72*2);      // 55296 -> 4 CTAs/SM
    const int smem2 = 3*2*(64*72*2)  + (128*72*2);      // 73728 -> 3 CTAs/SM
    const int smem3 = 1*2*(128*72*2) + (128*72*2);      // 55296 -> 4 CTAs/SM
    cudaFuncSetAttribute(gemm_mma<128, 64, 1, false, true , true>, cudaFuncAttributeMaxDynamicSharedMemorySize, smem1);
    cudaFuncSetAttribute(gemm_mma< 64, 64, 3, false, false, true>, cudaFuncAttributeMaxDynamicSharedMemorySize, smem2);
    cudaFuncSetAttribute(gemm_mma< 64,128, 1, true , false, true>, cudaFuncAttributeMaxDynamicSharedMemorySize, smem3);

    const int GEMM_GRID   = M / 128;           // 768
    const int SPMM_GRID   = V/2 * 32 / 256;    // 3072
    const int F16_GRID    = M*CMID/4/256;      // 6144
    const int BNR_GRID128 = M*CIN/4/256;       // 12288

    // ---- layer 1: y1h = fp16(x @ W1 + b1) ; fused stats+finalize ----
    gemm_mma<128, 64, 1, false, true, true><<<GEMM_GRID, 256, smem1>>>(
        x, nullptr, nullptr, W1, b1, nullptr, nullptr, y1h,
        g1, be1, gsum + 0, gsq + 0, gscale + 0, gshift + 0, ctr + 0);

    // ---- h1h = bnrelu(y1h) in fp16 ----
    bnrelu_h2h_kernel<<<F16_GRID, 256>>>(y1h, h1h, gscale + 0, gshift + 0);

    // ---- layer 2: Chebyshev K=3 in fp16 (pipelined exact-A GEMM) ----
    spmm_f16<false><<<SPMM_GRID, 256>>>(cols, vals, h1h, nullptr, t1h);   // t1 = S h1
    spmm_f16<true ><<<SPMM_GRID, 256>>>(cols, vals, t1h, h1h, t2h);       // t2 = 2 S t1 - h1
    gemm_mma<64, 64, 3, false, false, true><<<GEMM_GRID, 256, smem2>>>(
        h1h, t1h, t2h, W2, b2, nullptr, nullptr, y2h,
        g2, be2, gsum + 128, gsq + 128, gscale + 128, gshift + 128, ctr + 1);

    // ---- layer 3: y3h = fp16( bnrelu(y2h) @ W3 + b3 ) ; out = bnrelu(y3h) ----
    gemm_mma<64, 128, 1, true, false, true><<<GEMM_GRID, 256, smem3>>>(
        y2h, nullptr, nullptr, W3, b3, gscale + 128, gshift + 128, y3h,
        g3, be3, gsum + 256, gsq + 256, gscale + 256, gshift + 256, ctr + 2);
    bnrelu_out_kernel<CIN><<<BNR_GRID128, 256>>>(y3h, out, gscale + 256, gshift + 256);
}

// round 16
// speedup vs baseline: 1.1835x; 1.1549x over previous
#include <cuda_runtime.h>
#include <cuda_fp16.h>
#include <math.h>
#include <stdint.h>

#define V     49152
#define BATCH 2
#define M     (BATCH*V)      // 98304
#define DEG   20
#define CIN   128
#define CMID  64
#define SAp   72             // padded row stride (fp16 elems)

// ---------------- scratch (device globals; zero-initialized) ------------------
__device__ __align__(128) __half g_y1h[M*CMID];
__device__ __align__(128) __half g_h1h[M*CMID];
__device__ __align__(128) __half g_t1h[M*CMID];
__device__ __align__(128) __half g_t2h[M*CMID];
__device__ __align__(128) __half g_y2h[M*CMID];
__device__ __align__(128) __half g_y3h[M*CIN];
// preswizzled W images: [chunk][hi/lo][NOUT rows x SA cols]
__device__ __align__(128) __half g_w1p[2*2*64*SAp];    // K=128,NOUT=64  (36864B)
__device__ __align__(128) __half g_w2p[3*2*64*SAp];    // KT=192,NOUT=64 (55296B)
__device__ __align__(128) __half g_w3p[1*2*128*SAp];   // K=64, NOUT=128 (36864B)
__device__ __align__(128) float g_sum[3*128];
__device__ __align__(128) float g_sq [3*128];
__device__ __align__(128) float g_scale[3*128];
__device__ __align__(128) float g_shift[3*128];
__device__ unsigned int g_ctr[3];

// ---------------- PTX helpers --------------------------------------------------
__device__ __forceinline__ void mma_h(float* c, const uint32_t* a, const uint32_t* b) {
    asm volatile(
        "mma.sync.aligned.m16n8k16.row.col.f32.f16.f16.f32 "
        "{%0,%1,%2,%3}, {%4,%5,%6,%7}, {%8,%9}, {%0,%1,%2,%3};"
        : "+f"(c[0]), "+f"(c[1]), "+f"(c[2]), "+f"(c[3])
        : "r"(a[0]), "r"(a[1]), "r"(a[2]), "r"(a[3]), "r"(b[0]), "r"(b[1]));
}
__device__ __forceinline__ void ldsm_x4(uint32_t* r, uint32_t addr) {
    asm volatile("ldmatrix.sync.aligned.m8n8.x4.shared.b16 {%0,%1,%2,%3}, [%4];"
        : "=r"(r[0]), "=r"(r[1]), "=r"(r[2]), "=r"(r[3]) : "r"(addr));
}
__device__ __forceinline__ uint32_t smem_u32(const void* p) {
    uint32_t a;
    asm("{ .reg .u64 t; cvta.to.shared.u64 t, %1; cvt.u32.u64 %0, t; }" : "=r"(a) : "l"(p));
    return a;
}

// ---------------- W prep: fp32 -> preswizzled fp16 hi/lo images ----------------
__device__ __forceinline__ void w_prep_one(const float* __restrict__ W, __half* __restrict__ Wp,
                                           int idx, int NOUT) {
    int n = idx % NOUT, kt = idx / NOUT;
    int c = kt >> 6, kk = kt & 63;
    float w = W[idx];
    __half h = __float2half_rn(w);
    int tile = NOUT*SAp;
    Wp[c*2*tile + n*SAp + kk]        = h;
    Wp[c*2*tile + tile + n*SAp + kk] = __float2half_rn(w - __half2float(h));
}
__global__ void prep_w_kernel(const float* __restrict__ W1, const float* __restrict__ W2,
                              const float* __restrict__ W3) {
    int i = blockIdx.x * blockDim.x + threadIdx.x;
    if (i < 8192)                 w_prep_one(W1, g_w1p, i, 64);
    else if (i < 8192 + 12288)    w_prep_one(W2, g_w2p, i - 8192, 64);
    else if (i < 8192 + 12288 + 8192) w_prep_one(W3, g_w3p, i - 20480, 128);
}

// ---------------- tensor-core GEMM (HMMA fp16, chunked, ldmatrix x4) -----------
// Y[128-row tile, NOUT] = sum_s A_s[tile, K] @ W[s*K.., NOUT] + bias
// A: plain fp16 in smem; W: preswizzled fp16 hi/lo images -> 2 MMA passes.
// SRCF32: source is fp32 (converted while staging). BN0: fused BN+ReLU applied
// to source 0 while staging. OUTF16: Y stored as __half.
// Fused BN-stats epilogue (fp32 accumulators); last block computes this layer's
// scale/shift and resets the accumulators (replay-safe).
template<int K, int NOUT, int NSRC, bool BN0, bool SRCF32, bool OUTF16>
__global__ void __launch_bounds__(256) gemm_mma(
    const void* __restrict__ A0v, const void* __restrict__ A1v, const void* __restrict__ A2v,
    const __half* __restrict__ Wp, const float* __restrict__ bias,
    const float* __restrict__ bsc, const float* __restrict__ bsh,
    void* __restrict__ Yv,
    const float* __restrict__ gamma, const float* __restrict__ beta,
    float* __restrict__ gs, float* __restrict__ gq,
    float* __restrict__ oscale, float* __restrict__ oshift,
    unsigned int* __restrict__ ctr)
{
    constexpr int KT   = NSRC*K;
    constexpr int NCH  = KT/64;               // 64-col chunks
    constexpr int SA   = SAp;                 // padded row stride (fp16 elems)
    constexpr int WCH  = NOUT*SA*2;           // bytes per W chunk (hi or lo)
    constexpr int OFF_A = NCH*2*WCH;          // single A buffer after W chunks
    constexpr int WB16 = NCH*2*WCH/16;        // uint4 count of W image

    extern __shared__ char smc[];
    const uint32_t sbase = smem_u32(smc);

    const int t    = threadIdx.x;
    const int wid  = t >> 5, lane = t & 31;
    const int row0 = blockIdx.x * 128;
    const int g    = lane >> 2, tg = lane & 3;
    const int rb   = wid*16;

    // ---- stage W: raw uint4 copy of preswizzled image ----
    #pragma unroll
    for (int i = t; i < WB16; i += 256)
        ((uint4*)smc)[i] = ((const uint4*)Wp)[i];

    constexpr int NB = NOUT/8;
    float acc[NB][4];
    #pragma unroll
    for (int nb = 0; nb < NB; ++nb)
        acc[nb][0] = acc[nb][1] = acc[nb][2] = acc[nb][3] = 0.f;

    // lane-address pattern shared by A-frag x4 and W-frag x4 loads
    const uint32_t lpat = (((lane & 15))*SA + (lane >> 4)*8)*2;
    const uint32_t aAd  = sbase + OFF_A + rb*SA*2 + lpat;

    #pragma unroll
    for (int c = 0; c < NCH; ++c) {
        const int s  = (c*64) / K;
        const int ko = (c*64) % K;
        const void* Av = (s == 0) ? A0v : ((s == 1) ? A1v : A2v);

        __syncthreads();   // W staged (c==0) / previous chunk consumed
        if (!SRCF32) {
            const __half* A = (const __half*)Av;
            for (int i = t; i < 128*8; i += 256) {
                int r = i >> 3, c8 = i & 7;
                uint4 u = *(const uint4*)(A + (size_t)(row0 + r)*K + ko + c8*8);
                if (BN0 && s == 0) {
                    float4 sc0 = *(const float4*)(bsc + ko + c8*8);
                    float4 sc1 = *(const float4*)(bsc + ko + c8*8 + 4);
                    float4 sh0 = *(const float4*)(bsh + ko + c8*8);
                    float4 sh1 = *(const float4*)(bsh + ko + c8*8 + 4);
                    const __half2* hp = (const __half2*)&u;
                    float2 f0 = __half22float2(hp[0]);
                    float2 f1 = __half22float2(hp[1]);
                    float2 f2 = __half22float2(hp[2]);
                    float2 f3 = __half22float2(hp[3]);
                    __half2 o0 = __floats2half2_rn(fmaxf(fmaf(f0.x, sc0.x, sh0.x), 0.f),
                                                   fmaxf(fmaf(f0.y, sc0.y, sh0.y), 0.f));
                    __half2 o1 = __floats2half2_rn(fmaxf(fmaf(f1.x, sc0.z, sh0.z), 0.f),
                                                   fmaxf(fmaf(f1.y, sc0.w, sh0.w), 0.f));
                    __half2 o2 = __floats2half2_rn(fmaxf(fmaf(f2.x, sc1.x, sh1.x), 0.f),
                                                   fmaxf(fmaf(f2.y, sc1.y, sh1.y), 0.f));
                    __half2 o3 = __floats2half2_rn(fmaxf(fmaf(f3.x, sc1.z, sh1.z), 0.f),
                                                   fmaxf(fmaf(f3.y, sc1.w, sh1.w), 0.f));
                    u.x = *(uint32_t*)&o0; u.y = *(uint32_t*)&o1;
                    u.z = *(uint32_t*)&o2; u.w = *(uint32_t*)&o3;
                }
                *(uint4*)(smc + OFF_A + (r*SA + c8*8)*2) = u;
            }
        } else {
            const float* A = (const float*)Av;
            for (int i = t; i < 128*16; i += 256) {
                int r = i >> 4, c4 = i & 15;
                float4 v = *(const float4*)(A + (size_t)(row0 + r)*K + ko + c4*4);
                if (BN0 && s == 0) {
                    float4 sc = *(const float4*)(bsc + ko + c4*4);
                    float4 sh = *(const float4*)(bsh + ko + c4*4);
                    v.x = fmaxf(fmaf(v.x, sc.x, sh.x), 0.f);
                    v.y = fmaxf(fmaf(v.y, sc.y, sh.y), 0.f);
                    v.z = fmaxf(fmaf(v.z, sc.z, sh.z), 0.f);
                    v.w = fmaxf(fmaf(v.w, sc.w, sh.w), 0.f);
                }
                __half2 h01 = __floats2half2_rn(v.x, v.y);
                __half2 h23 = __floats2half2_rn(v.z, v.w);
                uint2 o; o.x = *(uint32_t*)&h01; o.y = *(uint32_t*)&h23;
                *(uint2*)(smc + OFF_A + (r*SA + c4*4)*2) = o;
            }
        }
        __syncthreads();

        const uint32_t wch = sbase + c*2*WCH + lpat;
        #pragma unroll
        for (int kk = 0; kk < 4; ++kk) {
            uint32_t ah[4];
            ldsm_x4(ah, aAd + kk*32);
            #pragma unroll
            for (int nb2 = 0; nb2 < NB/2; ++nb2) {
                uint32_t bh[4], bl[4];
                uint32_t wa = wch + nb2*16*SA*2 + kk*32;
                ldsm_x4(bh, wa);
                ldsm_x4(bl, wa + WCH);
                uint32_t b0h[2] = {bh[0], bh[2]}, b1h[2] = {bh[1], bh[3]};
                uint32_t b0l[2] = {bl[0], bl[2]}, b1l[2] = {bl[1], bl[3]};
                mma_h(acc[2*nb2],   ah, b0h);   // A*Whi
                mma_h(acc[2*nb2],   ah, b0l);   // A*Wlo
                mma_h(acc[2*nb2+1], ah, b1h);
                mma_h(acc[2*nb2+1], ah, b1l);
            }
        }
    }

    __syncthreads();   // compute done -> smem reusable for stats reduction
    float* redS = (float*)smc;               // [8][NOUT]
    float* redQ = (float*)smc + 8*NOUT;      // [8][NOUT]

    // ---- store (fp32 or fp16) + per-warp column partials (always fp32) ----
    {
        #pragma unroll
        for (int nb = 0; nb < NB; ++nb) {
            int c = nb*8 + tg*2;
            float2 bb = __ldg((const float2*)(bias + c));
            float y00 = acc[nb][0] + bb.x, y01 = acc[nb][1] + bb.y;
            float y80 = acc[nb][2] + bb.x, y81 = acc[nb][3] + bb.y;
            if (OUTF16) {
                __half* y0 = (__half*)Yv + (size_t)(row0 + rb + g)*NOUT;
                __half* y8 = (__half*)Yv + (size_t)(row0 + rb + g + 8)*NOUT;
                __half2 p0 = __floats2half2_rn(y00, y01);
                __half2 p8 = __floats2half2_rn(y80, y81);
                *(__half2*)(y0 + c) = p0;
                *(__half2*)(y8 + c) = p8;
            } else {
                float* y0 = (float*)Yv + (size_t)(row0 + rb + g)*NOUT;
                float* y8 = (float*)Yv + (size_t)(row0 + rb + g + 8)*NOUT;
                *(float2*)(y0 + c) = make_float2(y00, y01);
                *(float2*)(y8 + c) = make_float2(y80, y81);
            }
            float s0 = y00 + y80, q0 = y00*y00 + y80*y80;
            float s1 = y01 + y81, q1 = y01*y01 + y81*y81;
            #pragma unroll
            for (int off = 4; off <= 16; off <<= 1) {
                s0 += __shfl_xor_sync(0xffffffffu, s0, off);
                q0 += __shfl_xor_sync(0xffffffffu, q0, off);
                s1 += __shfl_xor_sync(0xffffffffu, s1, off);
                q1 += __shfl_xor_sync(0xffffffffu, q1, off);
            }
            if (lane < 4) {
                redS[wid*NOUT + c]     = s0;
                redS[wid*NOUT + c + 1] = s1;
                redQ[wid*NOUT + c]     = q0;
                redQ[wid*NOUT + c + 1] = q1;
            }
        }
    }
    __syncthreads();

    if (t < NOUT) {
        float s = 0.f, q = 0.f;
        #pragma unroll
        for (int w = 0; w < 8; ++w) { s += redS[w*NOUT + t]; q += redQ[w*NOUT + t]; }
        atomicAdd(&gs[t], s);
        atomicAdd(&gq[t], q);
    }
    __threadfence();
    __syncthreads();

    __shared__ bool s_last;
    if (t == 0) s_last = (atomicAdd(ctr, 1u) == (unsigned)gridDim.x - 1u);
    __syncthreads();
    if (s_last) {
        if (t < NOUT) {
            float mean = gs[t] * (1.f/(float)M);
            float var  = gq[t] * (1.f/(float)M) - mean*mean;
            float sc   = gamma[t] * rsqrtf(var + 1e-5f);
            oscale[t] = sc;
            oshift[t] = beta[t] - mean*sc;
            gs[t] = 0.f; gq[t] = 0.f;      // replay-safe reset
        }
        if (t == 0) *ctr = 0u;
    }
}

// ---------------- SpMM fp16: 2 rows/warp, 8 fp16 channels/lane (R13 form) ------
template<bool CHEB>
__global__ void spmm_f16(const int*   __restrict__ cols,
                         const float* __restrict__ vals,
                         const __half* __restrict__ X,
                         const __half* __restrict__ X0h,
                         __half* __restrict__ Yo)
{
    int warp = (blockIdx.x * blockDim.x + threadIdx.x) >> 5;
    int lane = threadIdx.x & 31;
    int r = warp*2 + (lane >> 4);
    if (r >= V) return;
    const int b  = (lane >> 3) & 1;
    const int f8 = lane & 7;
    const __half* Xb = X + (size_t)b*V*CMID + f8*8;

    float acc[8];
    #pragma unroll
    for (int j = 0; j < 8; ++j) acc[j] = 0.f;

    {
        int c = __ldg(&cols[r]); float v = __ldg(&vals[r]);
        uint4 u = *(const uint4*)(Xb + (size_t)c*CMID);
        const __half2* hp = (const __half2*)&u;
        #pragma unroll
        for (int j = 0; j < 4; ++j) {
            float2 f = __half22float2(hp[j]);
            acc[2*j]   += v*f.x;
            acc[2*j+1] += v*f.y;
        }
    }
    const int base = V + r*DEG;
    #pragma unroll
    for (int d = 0; d < DEG; ++d) {
        int c = __ldg(&cols[base+d]); float v = __ldg(&vals[base+d]);
        uint4 u = *(const uint4*)(Xb + (size_t)c*CMID);
        const __half2* hp = (const __half2*)&u;
        #pragma unroll
        for (int j = 0; j < 4; ++j) {
            float2 f = __half22float2(hp[j]);
            acc[2*j]   += v*f.x;
            acc[2*j+1] += v*f.y;
        }
    }

    size_t o = (size_t)b*V*CMID + (size_t)r*CMID + f8*8;
    if (CHEB) {
        uint4 u0 = *(const uint4*)(X0h + o);
        const __half2* hp = (const __half2*)&u0;
        #pragma unroll
        for (int j = 0; j < 4; ++j) {
            float2 f = __half22float2(hp[j]);
            acc[2*j]   = 2.f*acc[2*j]   - f.x;
            acc[2*j+1] = 2.f*acc[2*j+1] - f.y;
        }
    }
    __half2 outp[4];
    #pragma unroll
    for (int j = 0; j < 4; ++j) outp[j] = __floats2half2_rn(acc[2*j], acc[2*j+1]);
    *(uint4*)(Yo + o) = *(uint4*)outp;
}

// ---------------- BN apply + ReLU: fp16 in -> fp16 out (layer-1) ---------------
__global__ void bnrelu_h2h_kernel(const __half* __restrict__ Yin,
                                  __half* __restrict__ H,
                                  const float* __restrict__ scale,
                                  const float* __restrict__ shift)
{
    int i4 = blockIdx.x * blockDim.x + threadIdx.x;
    constexpr int TOT4 = M*CMID/4;
    if (i4 >= TOT4) return;
    int c4 = i4 & (CMID/4 - 1);
    uint2 u = ((const uint2*)Yin)[i4];
    const __half2* hp = (const __half2*)&u;
    float2 f0 = __half22float2(hp[0]);
    float2 f1 = __half22float2(hp[1]);
    float4 sc = ((const float4*)scale)[c4];
    float4 sh = ((const float4*)shift)[c4];
    __half2 a = __floats2half2_rn(fmaxf(fmaf(f0.x, sc.x, sh.x), 0.f),
                                  fmaxf(fmaf(f0.y, sc.y, sh.y), 0.f));
    __half2 b = __floats2half2_rn(fmaxf(fmaf(f1.x, sc.z, sh.z), 0.f),
                                  fmaxf(fmaf(f1.y, sc.w, sh.w), 0.f));
    uint2 o; o.x = *(uint32_t*)&a; o.y = *(uint32_t*)&b;
    ((uint2*)H)[i4] = o;
}

// ---------------- final BN apply + ReLU: fp16 in -> fp32 out -------------------
template<int C>
__global__ void bnrelu_out_kernel(const __half* __restrict__ Yin,
                                  float* __restrict__ Out,
                                  const float* __restrict__ scale,
                                  const float* __restrict__ shift)
{
    int i4 = blockIdx.x * blockDim.x + threadIdx.x;
    constexpr int TOT4 = M*C/4;
    if (i4 >= TOT4) return;
    int c4 = i4 % (C/4);
    uint2 u = ((const uint2*)Yin)[i4];
    const __half2* hp = (const __half2*)&u;
    float2 f0 = __half22float2(hp[0]);
    float2 f1 = __half22float2(hp[1]);
    float4 sc = ((const float4*)scale)[c4];
    float4 sh = ((const float4*)shift)[c4];
    float4 o;
    o.x = fmaxf(fmaf(f0.x, sc.x, sh.x), 0.f);
    o.y = fmaxf(fmaf(f0.y, sc.y, sh.y), 0.f);
    o.z = fmaxf(fmaf(f1.x, sc.z, sh.z), 0.f);
    o.w = fmaxf(fmaf(f1.y, sc.w, sh.w), 0.f);
    ((float4*)Out)[i4] = o;
}

// ------------------------------------------------------------------------------
extern "C" void kernel_launch(void* const* d_in, const int* in_sizes, int n_in,
                              void* d_out, int out_size)
{
    const float* x    = (const float*)d_in[0];
    const int*   cols = (const int*)  d_in[2];
    const float* vals = (const float*)d_in[3];
    const float* W1   = (const float*)d_in[4];
    const float* b1   = (const float*)d_in[5];
    const float* g1   = (const float*)d_in[6];
    const float* be1  = (const float*)d_in[7];
    const float* W2   = (const float*)d_in[8];
    const float* b2   = (const float*)d_in[9];
    const float* g2   = (const float*)d_in[10];
    const float* be2  = (const float*)d_in[11];
    const float* W3   = (const float*)d_in[12];
    const float* b3   = (const float*)d_in[13];
    const float* g3   = (const float*)d_in[14];
    const float* be3  = (const float*)d_in[15];
    float* out = (float*)d_out;

    float *gsum, *gsq, *gscale, *gshift;
    __half *y1h, *h1h, *t1h, *t2h, *y2h, *y3h, *w1p, *w2p, *w3p;
    unsigned int* ctr;
    cudaGetSymbolAddress((void**)&y1h, g_y1h);
    cudaGetSymbolAddress((void**)&h1h, g_h1h);
    cudaGetSymbolAddress((void**)&t1h, g_t1h);
    cudaGetSymbolAddress((void**)&t2h, g_t2h);
    cudaGetSymbolAddress((void**)&y2h, g_y2h);
    cudaGetSymbolAddress((void**)&y3h, g_y3h);
    cudaGetSymbolAddress((void**)&w1p, g_w1p);
    cudaGetSymbolAddress((void**)&w2p, g_w2p);
    cudaGetSymbolAddress((void**)&w3p, g_w3p);
    cudaGetSymbolAddress((void**)&gsum,   g_sum);
    cudaGetSymbolAddress((void**)&gsq,    g_sq);
    cudaGetSymbolAddress((void**)&gscale, g_scale);
    cudaGetSymbolAddress((void**)&gshift, g_shift);
    cudaGetSymbolAddress((void**)&ctr,    g_ctr);

    // smem (SA=72): W image (hi+lo per chunk) + single fp16 A buffer (18432 B)
    const int smem1 = 2*2*(64*72*2)  + (128*72*2);      // 55296 -> 4 CTAs/SM
    const int smem2 = 3*2*(64*72*2)  + (128*72*2);      // 73728 -> 3 CTAs/SM
    const int smem3 = 1*2*(128*72*2) + (128*72*2);      // 55296 -> 4 CTAs/SM
    cudaFuncSetAttribute(gemm_mma<128, 64, 1, false, true , true>, cudaFuncAttributeMaxDynamicSharedMemorySize, smem1);
    cudaFuncSetAttribute(gemm_mma< 64, 64, 3, false, false, true>, cudaFuncAttributeMaxDynamicSharedMemorySize, smem2);
    cudaFuncSetAttribute(gemm_mma< 64,128, 1, true , false, true>, cudaFuncAttributeMaxDynamicSharedMemorySize, smem3);

    const int GEMM_GRID   = M / 128;           // 768
    const int SPMM_GRID   = V/2 * 32 / 256;    // 3072
    const int F16_GRID    = M*CMID/4/256;      // 6144
    const int BNR_GRID128 = M*CIN/4/256;       // 12288

    // ---- W prep: preswizzled fp16 hi/lo images (tiny) ----
    prep_w_kernel<<<112, 256>>>(W1, W2, W3);

    // ---- layer 1: y1h = fp16(x @ W1 + b1) ; fused stats+finalize ----
    gemm_mma<128, 64, 1, false, true, true><<<GEMM_GRID, 256, smem1>>>(
        x, nullptr, nullptr, w1p, b1, nullptr, nullptr, y1h,
        g1, be1, gsum + 0, gsq + 0, gscale + 0, gshift + 0, ctr + 0);

    // ---- h1h = bnrelu(y1h) in fp16 ----
    bnrelu_h2h_kernel<<<F16_GRID, 256>>>(y1h, h1h, gscale + 0, gshift + 0);

    // ---- layer 2: Chebyshev K=3 in fp16 ----
    spmm_f16<false><<<SPMM_GRID, 256>>>(cols, vals, h1h, nullptr, t1h);   // t1 = S h1
    spmm_f16<true ><<<SPMM_GRID, 256>>>(cols, vals, t1h, h1h, t2h);       // t2 = 2 S t1 - h1
    gemm_mma<64, 64, 3, false, false, true><<<GEMM_GRID, 256, smem2>>>(
        h1h, t1h, t2h, w2p, b2, nullptr, nullptr, y2h,
        g2, be2, gsum + 128, gsq + 128, gscale + 128, gshift + 128, ctr + 1);

    // ---- layer 3: y3h = fp16( bnrelu(y2h) @ W3 + b3 ) ; out = bnrelu(y3h) ----
    gemm_mma<64, 128, 1, true, false, true><<<GEMM_GRID, 256, smem3>>>(
        y2h, nullptr, nullptr, w3p, b3, gscale + 128, gshift + 128, y3h,
        g3, be3, gsum + 256, gsq + 256, gscale + 256, gshift + 256, ctr + 2);
    bnrelu_out_kernel<CIN><<<BNR_GRID128, 256>>>(y3h, out, gscale + 256, gshift + 256);
}